// round 15
// baseline (speedup 1.0000x reference)
#include <cuda_runtime.h>
#include <cuda_bf16.h>
#include <cstdint>

#define CDIV(a,b) (((a)+(b)-1)/(b))

constexpr int Nn  = 50000;
constexpr int Ed  = 256;
constexpr int Hd  = 512;
constexpr int NEx = 5;
constexpr int GHd = 128;
constexpr int EDGES_MAX = 800000;

// ---------------- scratch (static device globals; no allocation) -------------
__device__ float g_ghid[(size_t)Nn * GHd];
__device__ int   g_lists[NEx * Nn];
__device__ float g_gatew[NEx * Nn];
__device__ int   g_slot[2 * Nn];                    // per-node assignment slots
__device__ int   g_counts[NEx];
__device__ float g_h1[(size_t)NEx * Nn * Hd];
__device__ float g_eout[(size_t)NEx * Nn * Hd];     // dense expert-2 output
__device__ float g_nf[(size_t)Nn * Hd];
__device__ float g_msg[(size_t)Nn * Hd];
__device__ float g_hl[(size_t)Nn * Hd];

// CSR for edge segment-sum
__device__ int g_deg[Nn];
__device__ int g_off[Nn + 1];
__device__ int g_cur[Nn];
__device__ int g_esrc[EDGES_MAX];

// pre-split weights, [n][k] layout, bf16 hi/lo planes
constexpr size_t OFF_G   = 0;                       // 128 x 768
constexpr size_t OFF_E1  = 98304;                   // 5 x 512 x 256
constexpr size_t OFF_E2  = 753664;                  // 5 x 512 x 512
constexpr size_t OFF_GNN = 2064384;                 // 2 x 512 x 1024
constexpr size_t WTOT    = 3112960;
__device__ __nv_bfloat16 g_wbh[WTOT];
__device__ __nv_bfloat16 g_wbl[WTOT];

// ---------------- helpers ----------------------------------------------------
__device__ __forceinline__ float gelu_f(float x) {
    float t = tanhf(0.7978845608028654f * (x + 0.044715f * x * x * x));
    return 0.5f * x * (1.0f + t);
}

__device__ __forceinline__ uint32_t packbf(float lo, float hi) {
    __nv_bfloat162 h = __floats2bfloat162_rn(lo, hi);
    return *reinterpret_cast<uint32_t*>(&h);
}

__device__ __forceinline__ uint32_t smem_u32(const void* p) {
    uint32_t a;
    asm("{ .reg .u64 t; cvta.to.shared.u64 t, %1; cvt.u32.u64 %0, t; }"
        : "=r"(a) : "l"(p));
    return a;
}

__device__ __forceinline__ void mma16816(
    float (&c)[4], const uint32_t (&a)[4], const uint32_t (&b)[2])
{
    asm volatile(
        "mma.sync.aligned.m16n8k16.row.col.f32.bf16.bf16.f32 "
        "{%0,%1,%2,%3}, {%4,%5,%6,%7}, {%8,%9}, {%0,%1,%2,%3};"
        : "+f"(c[0]), "+f"(c[1]), "+f"(c[2]), "+f"(c[3])
        : "r"(a[0]), "r"(a[1]), "r"(a[2]), "r"(a[3]), "r"(b[0]), "r"(b[1]));
}

__device__ __forceinline__ void ldm_x4(uint32_t (&r)[4], uint32_t addr) {
    asm volatile("ldmatrix.sync.aligned.m8n8.x4.shared.b16 {%0,%1,%2,%3}, [%4];"
                 : "=r"(r[0]), "=r"(r[1]), "=r"(r[2]), "=r"(r[3]) : "r"(addr));
}

// ---------------- weight prep: transpose + bf16 hi/lo split ------------------
__global__ void k_wprep(const float* __restrict__ W,
                        __nv_bfloat16* __restrict__ oh,
                        __nv_bfloat16* __restrict__ ol,
                        int Kw, int N, int ldk)
{
    int b = blockIdx.y;
    const float* Wp = W + (size_t)b * Kw * N;
    __nv_bfloat16* ohp = oh + (size_t)b * N * ldk;
    __nv_bfloat16* olp = ol + (size_t)b * N * ldk;
    int idx = blockIdx.x * blockDim.x + threadIdx.x;
    if (idx >= Kw * N) return;
    int k = idx / N, n = idx - k * N;
    float x = Wp[idx];
    __nv_bfloat16 h = __float2bfloat16(x);
    ohp[(size_t)n * ldk + k] = h;
    olp[(size_t)n * ldk + k] = __float2bfloat16(x - __bfloat162float(h));
}

// ---------------- bf16x3 tensor-core GEMM (128xNT tile, BK=32) ---------------
// NT = 128: warp tile 64x32 (nj<4); NT = 256: warp tile 64x64 (nj<8).
// 256 thr = 8 warps (2x4), ldmatrix fragments, double-buffered smem,
// pre-split B, 3-pass hi/lo accumulation, in-loop A split.
template<int NT, int NSRC, bool ESEL, bool AEXP, bool GATHER, int ACT, bool EXPERT>
__global__ void __launch_bounds__(256) k_mma(
    const float* __restrict__ A0, const float* __restrict__ A1,
    const float* __restrict__ A2,
    const __nv_bfloat16* __restrict__ Bh, const __nv_bfloat16* __restrict__ Bl,
    const float* __restrict__ bias, float* __restrict__ C,
    const int* __restrict__ rowlist,
    int Mfixed, int K, int NC)
{
    constexpr int NJ   = NT / 32;          // n-fragments per warp (4 or 8)
    constexpr int PBAe = 5120;             // A plane elems (128*40)
    constexpr int PBBe = NT * 40;          // B plane elems
    constexpr int STGe = 2 * PBAe + 2 * PBBe;   // stage elems
    constexpr int TPR  = 256 / NT;         // threads per B row (2 or 1)
    constexpr int NV   = 4 / TPR;          // uint4 per B plane per thread

    int M;
    const __nv_bfloat16* Bhp = Bh;
    const __nv_bfloat16* Blp = Bl;
    const float* biasp = bias;
    float*       Cp    = C;
    const int*   rl    = rowlist;
    const float* Asel  = A0;
    if (EXPERT) {
        int e = blockIdx.z;
        M = g_counts[e]; if (M > Nn) M = Nn;
        Bhp = Bh + (size_t)e * (size_t)NC * K;
        Blp = Bl + (size_t)e * (size_t)NC * K;
        if (bias) biasp = bias + (size_t)e * NC;
        if (ESEL) {
            const int map[NEx] = { 1, 2, 0, 0, 2 };  // tab, str, text, text, str
            int s = map[e];
            Asel = (s == 0) ? A0 : ((s == 1) ? A1 : A2);
        }
        if (AEXP) Asel = A0 + (size_t)e * (size_t)Nn * K;
        rl = rowlist + e * Nn;
        Cp = C + (size_t)e * (size_t)Nn * NC;
    } else {
        M = Mfixed;
    }
    if ((int)(blockIdx.y * 128) >= M) return;

    extern __shared__ __nv_bfloat16 sm[];
    const uint32_t smb = smem_u32(sm);

    const int tid  = threadIdx.x;
    const int warp = tid >> 5, lane = tid & 31;
    const int wm = warp >> 2, wn = warp & 3;      // warp tile: 64 x (NT/4)
    const int gid = lane >> 2, tig = lane & 3;
    const int row0 = blockIdx.y * 128;
    const int col0 = blockIdx.x * NT;

    // ---- A loader: row am, 16 k-values at ak ----
    const int am = tid >> 1;
    const int ak = (tid & 1) << 4;
    const bool avalid = (row0 + am) < M;
    int arow = row0 + am;
    if (GATHER) {
        arow = avalid ? rl[arow] : 0;
        if ((unsigned)arow >= (unsigned)Nn) arow = 0;
    } else if (!avalid) arow = 0;

    auto aload = [&](int k0, float4 (&d)[4]) {
        if (!avalid) {
            d[0] = d[1] = d[2] = d[3] = make_float4(0.f, 0.f, 0.f, 0.f);
            return;
        }
        int kg = k0 + ak;
        const float* p;
        if (NSRC == 3) {
            const float* s = (kg < 256) ? A0 : ((kg < 512) ? A1 : A2);
            p = s + (size_t)arow * 256 + (kg & 255);
        } else if (NSRC == 2) {
            const float* s = (kg < 512) ? A0 : A1;
            p = s + (size_t)arow * 512 + (kg & 511);
        } else {
            p = Asel + (size_t)arow * (size_t)K + kg;
        }
        #pragma unroll
        for (int q = 0; q < 4; q++) d[q] = *(const float4*)(p + q * 4);
    };

    // ---- B loader: pre-split bf16, [n][k], fully coalesced ----
    const int bn = tid / TPR;
    const int bk = (tid % TPR) * 16;
    const __nv_bfloat16* bhrow = Bhp + (size_t)(col0 + bn) * K + bk;
    const __nv_bfloat16* blrow = Blp + (size_t)(col0 + bn) * K + bk;
    auto bload = [&](int k0, uint4 (&dh)[NV], uint4 (&dl)[NV]) {
        const uint4* ph = (const uint4*)(bhrow + k0);
        const uint4* pl = (const uint4*)(blrow + k0);
        #pragma unroll
        for (int v = 0; v < NV; v++) { dh[v] = ph[v]; dl[v] = pl[v]; }
    };

    // ---- stage regs -> smem (split A into hi/lo, copy B) ----
    auto store = [&](int b, const float4 (&av)[4], const uint4 (&bvh)[NV],
                     const uint4 (&bvl)[NV]) {
        __nv_bfloat16* base = sm + (size_t)b * STGe;
        uint32_t* ah = (uint32_t*)(base + am * 40 + ak);
        uint32_t* al = (uint32_t*)(base + PBAe + am * 40 + ak);
        #pragma unroll
        for (int q = 0; q < 4; q++) {
            float4 v = av[q];
            uint32_t hp0 = packbf(v.x, v.y);
            uint32_t hp1 = packbf(v.z, v.w);
            __nv_bfloat162 h0 = *reinterpret_cast<__nv_bfloat162*>(&hp0);
            __nv_bfloat162 h1 = *reinterpret_cast<__nv_bfloat162*>(&hp1);
            ah[q * 2]     = hp0;
            ah[q * 2 + 1] = hp1;
            al[q * 2]     = packbf(v.x - __low2float(h0), v.y - __high2float(h0));
            al[q * 2 + 1] = packbf(v.z - __low2float(h1), v.w - __high2float(h1));
        }
        __nv_bfloat16* bb = base + 2 * PBAe + bn * 40 + bk;
        #pragma unroll
        for (int v = 0; v < NV; v++) {
            *(uint4*)(bb + v * 8)        = bvh[v];
            *(uint4*)(bb + PBBe + v * 8) = bvl[v];
        }
    };

    float c[4][NJ][4];
    #pragma unroll
    for (int i = 0; i < 4; i++)
        #pragma unroll
        for (int j = 0; j < NJ; j++)
            #pragma unroll
            for (int q = 0; q < 4; q++) c[i][j][q] = 0.f;

    const int ltr = lane & 7;
    const int lt8 = ((lane >> 3) & 1) * 8;
    const int lk8 = (lane >> 4) * 8;

    auto compute = [&](int b) {
        const uint32_t sbase = smb + (uint32_t)b * STGe * 2;
        #pragma unroll
        for (int ks = 0; ks < 32; ks += 16) {
            uint32_t bfh[NJ][2], bfl[NJ][2];
            #pragma unroll
            for (int jp = 0; jp < NJ / 2; jp++) {
                int nrow = wn * (NT / 4) + (jp * 2 + (lane >> 4)) * 8 + ltr;
                int koff = ks + ((lane >> 3) & 1) * 8;
                uint32_t addr = sbase + 4 * PBAe + (uint32_t)(nrow * 40 + koff) * 2;
                uint32_t r[4];
                ldm_x4(r, addr);
                bfh[jp*2][0] = r[0]; bfh[jp*2][1] = r[1];
                bfh[jp*2+1][0] = r[2]; bfh[jp*2+1][1] = r[3];
                ldm_x4(r, addr + 2 * PBBe);
                bfl[jp*2][0] = r[0]; bfl[jp*2][1] = r[1];
                bfl[jp*2+1][0] = r[2]; bfl[jp*2+1][1] = r[3];
            }
            #pragma unroll
            for (int mi = 0; mi < 4; mi++) {
                int mrow = wm * 64 + mi * 16 + lt8 + ltr;
                int koff = ks + lk8;
                uint32_t addr = sbase + (uint32_t)(mrow * 40 + koff) * 2;
                uint32_t ah[4], al[4];
                ldm_x4(ah, addr);
                ldm_x4(al, addr + 2 * PBAe);
                #pragma unroll
                for (int nj = 0; nj < NJ; nj++) {
                    mma16816(c[mi][nj], ah, bfh[nj]);   // Ah*Bh
                    mma16816(c[mi][nj], ah, bfl[nj]);   // Ah*Bl
                    mma16816(c[mi][nj], al, bfh[nj]);   // Al*Bh
                }
            }
        }
    };

    const int nch = K >> 5;
    float4 apre[4]; uint4 bph[NV], bpl[NV];
    aload(0, apre); bload(0, bph, bpl);
    store(0, apre, bph, bpl);
    __syncthreads();

    for (int ch = 0; ch < nch; ch++) {
        if (ch + 1 < nch) { aload((ch + 1) << 5, apre); bload((ch + 1) << 5, bph, bpl); }
        compute(ch & 1);
        if (ch + 1 < nch) {
            store((ch + 1) & 1, apre, bph, bpl);
            __syncthreads();
        }
    }

    // ---- epilogue: dense float2 stores ----
    #pragma unroll
    for (int mi = 0; mi < 4; mi++) {
        #pragma unroll
        for (int h = 0; h < 2; h++) {
            int rg = row0 + wm * 64 + mi * 16 + gid + h * 8;
            if (rg >= M) continue;
            #pragma unroll
            for (int nj = 0; nj < NJ; nj++) {
                int col = col0 + wn * (NT / 4) + nj * 8 + tig * 2;
                float vx = c[mi][nj][h * 2 + 0];
                float vy = c[mi][nj][h * 2 + 1];
                if (biasp) { vx += biasp[col]; vy += biasp[col + 1]; }
                if (ACT == 1) { vx = fmaxf(vx, 0.f); vy = fmaxf(vy, 0.f); }
                else if (ACT == 2) { vx = gelu_f(vx); vy = gelu_f(vy); }
                *(float2*)(Cp + (size_t)rg * NC + col) = make_float2(vx, vy);
            }
        }
    }
}

// ---------------- gating head: logits -> top2 -> routing lists + slots -------
__global__ void k_gate(const float* __restrict__ Wg2, const float* __restrict__ bg2) {
    __shared__ int   scnt[NEx], sbase[NEx];
    __shared__ int   se[64];
    __shared__ int   snode[64];
    __shared__ int   spos[64];
    __shared__ float sg[64];

    const int tid = threadIdx.x;
    if (tid < NEx) scnt[tid] = 0;
    __syncthreads();

    const int warp = tid >> 5, lane = tid & 31;
    const int node = blockIdx.x * 32 + warp;

    if (node < Nn) {
        const float* gr = g_ghid + (size_t)node * GHd;
        float v0 = gr[lane], v1 = gr[lane + 32], v2 = gr[lane + 64], v3 = gr[lane + 96];
        float l[NEx];
        #pragma unroll
        for (int e = 0; e < NEx; e++) {
            float p = v0 * Wg2[lane * NEx + e]
                    + v1 * Wg2[(lane + 32) * NEx + e]
                    + v2 * Wg2[(lane + 64) * NEx + e]
                    + v3 * Wg2[(lane + 96) * NEx + e];
            #pragma unroll
            for (int off = 16; off > 0; off >>= 1)
                p += __shfl_xor_sync(0xffffffffu, p, off);
            l[e] = p;
        }
        if (lane == 0) {
            #pragma unroll
            for (int e = 0; e < NEx; e++) l[e] += bg2[e];
            int e0 = 0;
            #pragma unroll
            for (int e = 1; e < NEx; e++) if (l[e] > l[e0]) e0 = e;
            int e1 = -1;
            #pragma unroll
            for (int e = 0; e < NEx; e++)
                if (e != e0 && (e1 < 0 || l[e] > l[e1])) e1 = e;
            float gate0 = 1.f / (1.f + expf(l[e1] - l[e0]));
            float gate1 = 1.f - gate0;
            int s0 = warp * 2, s1 = warp * 2 + 1;
            se[s0] = e0; snode[s0] = node; sg[s0] = gate0;
            spos[s0] = atomicAdd(&scnt[e0], 1);
            se[s1] = e1; snode[s1] = node; sg[s1] = gate1;
            spos[s1] = atomicAdd(&scnt[e1], 1);
        }
    } else if (lane == 0) {
        se[warp * 2] = -1; se[warp * 2 + 1] = -1;
    }
    __syncthreads();
    if (tid < NEx) sbase[tid] = atomicAdd(&g_counts[tid], scnt[tid]);
    __syncthreads();
    if (tid < 64 && se[tid] >= 0) {
        int e = se[tid];
        int p = sbase[e] + spos[tid];
        if (p >= 0 && p < Nn) {
            g_lists[e * Nn + p] = snode[tid];
            g_gatew[e * Nn + p] = sg[tid];
            g_slot[snode[tid] * 2 + (tid & 1)] = e * Nn + p;
        }
    }
}

// ---------------- combine: nf[n] = g0*eout[slot0] + g1*eout[slot1] -----------
__global__ void __launch_bounds__(128) k_combine() {
    const int n = blockIdx.x;
    const int t = threadIdx.x;            // float4 lane, 128 per row
    int s0 = g_slot[n * 2], s1 = g_slot[n * 2 + 1];
    if ((unsigned)s0 >= (unsigned)(NEx * Nn)) s0 = 0;
    if ((unsigned)s1 >= (unsigned)(NEx * Nn)) s1 = 0;
    float g0 = g_gatew[s0], g1 = g_gatew[s1];
    float4 a = ((const float4*)(g_eout + (size_t)s0 * Hd))[t];
    float4 b = ((const float4*)(g_eout + (size_t)s1 * Hd))[t];
    float4 r;
    r.x = g0 * a.x + g1 * b.x;
    r.y = g0 * a.y + g1 * b.y;
    r.z = g0 * a.z + g1 * b.z;
    r.w = g0 * a.w + g1 * b.w;
    ((float4*)(g_nf + (size_t)n * Hd))[t] = r;
}

// ---------------- CSR build: hist -> scan -> fill -----------------------------
__global__ void k_hist(const int* __restrict__ ei, int nedges) {
    int e = blockIdx.x * blockDim.x + threadIdx.x;
    if (e >= nedges) return;
    int d = ei[nedges + e];
    if ((unsigned)d < (unsigned)Nn) atomicAdd(&g_deg[d], 1);
}

__global__ void k_scan(int n) {
    __shared__ int sw[32];
    __shared__ int scarry;
    const int tid = threadIdx.x;
    const int lane = tid & 31, warp = tid >> 5;
    if (tid == 0) scarry = 0;
    __syncthreads();
    for (int base = 0; base < n; base += 1024) {
        int i = base + tid;
        int v = (i < n) ? g_deg[i] : 0;
        int x = v;
        #pragma unroll
        for (int o = 1; o < 32; o <<= 1) {
            int y = __shfl_up_sync(0xffffffffu, x, o);
            if (lane >= o) x += y;
        }
        if (lane == 31) sw[warp] = x;
        __syncthreads();
        if (warp == 0) {
            int s = sw[lane];
            #pragma unroll
            for (int o = 1; o < 32; o <<= 1) {
                int y = __shfl_up_sync(0xffffffffu, s, o);
                if (lane >= o) s += y;
            }
            sw[lane] = s;
        }
        __syncthreads();
        int incl  = x + (warp ? sw[warp - 1] : 0);
        int carry = scarry;
        if (i < n) g_off[i] = carry + incl - v;   // exclusive
        int total = sw[31];
        __syncthreads();
        if (tid == 0) scarry = carry + total;
        __syncthreads();
    }
    if (tid == 0) g_off[n] = scarry;
}

__global__ void k_fill(const int* __restrict__ ei, int nedges) {
    int e = blockIdx.x * blockDim.x + threadIdx.x;
    if (e >= nedges) return;
    int s = ei[e];
    int d = ei[nedges + e];
    if ((unsigned)s >= (unsigned)Nn || (unsigned)d >= (unsigned)Nn) return;
    int pos = atomicAdd(&g_cur[d], 1);
    if ((unsigned)pos < (unsigned)EDGES_MAX) g_esrc[pos] = s;
}

// ---------------- CSR gather: msg[d] = sum_{e: dst=d} h[src[e]] ---------------
__global__ void __launch_bounds__(128) k_gather(
    const float* __restrict__ h, float* __restrict__ msg)
{
    const int d = blockIdx.x;
    const int t = threadIdx.x;            // float4 lane, 128 per row
    int beg = g_off[d], end = g_off[d + 1];
    float4 acc = make_float4(0.f, 0.f, 0.f, 0.f);
    int i = beg;
    for (; i + 3 < end; i += 4) {
        int s0 = g_esrc[i],     s1 = g_esrc[i + 1];
        int s2 = g_esrc[i + 2], s3 = g_esrc[i + 3];
        float4 v0 = ((const float4*)(h + (size_t)s0 * Hd))[t];
        float4 v1 = ((const float4*)(h + (size_t)s1 * Hd))[t];
        float4 v2 = ((const float4*)(h + (size_t)s2 * Hd))[t];
        float4 v3 = ((const float4*)(h + (size_t)s3 * Hd))[t];
        acc.x += (v0.x + v1.x) + (v2.x + v3.x);
        acc.y += (v0.y + v1.y) + (v2.y + v3.y);
        acc.z += (v0.z + v1.z) + (v2.z + v3.z);
        acc.w += (v0.w + v1.w) + (v2.w + v3.w);
    }
    for (; i < end; i++) {
        int s0 = g_esrc[i];
        float4 v0 = ((const float4*)(h + (size_t)s0 * Hd))[t];
        acc.x += v0.x; acc.y += v0.y; acc.z += v0.z; acc.w += v0.w;
    }
    ((float4*)(msg + (size_t)d * Hd))[t] = acc;
}

// ---------------- launch -----------------------------------------------------
extern "C" void kernel_launch(void* const* d_in, const int* in_sizes, int n_in,
                              void* d_out, int out_size)
{
    const float* text = (const float*)d_in[0];
    const float* tab  = (const float*)d_in[1];
    const float* str  = (const float*)d_in[2];
    const int*   ei   = (const int*)d_in[3];
    const float* Wg1  = (const float*)d_in[4];
    const float* bg1  = (const float*)d_in[5];
    const float* Wg2  = (const float*)d_in[6];
    const float* bg2  = (const float*)d_in[7];
    const float* We1  = (const float*)d_in[8];
    const float* be1  = (const float*)d_in[9];
    const float* We2  = (const float*)d_in[10];
    const float* be2  = (const float*)d_in[11];
    const float* Wself = (const float*)d_in[12];
    const float* Wnbr  = (const float*)d_in[13];
    float* out = (float*)d_out;
    const int nedges = in_sizes[3] / 2;

    void *pcnt, *pghid, *pnf, *pmsg, *phl, *ph1, *peo, *plists, *pwh, *pwl;
    void *pdeg, *poff, *pcur;
    cudaGetSymbolAddress(&pcnt,   g_counts);
    cudaGetSymbolAddress(&pghid,  g_ghid);
    cudaGetSymbolAddress(&pnf,    g_nf);
    cudaGetSymbolAddress(&pmsg,   g_msg);
    cudaGetSymbolAddress(&phl,    g_hl);
    cudaGetSymbolAddress(&ph1,    g_h1);
    cudaGetSymbolAddress(&peo,    g_eout);
    cudaGetSymbolAddress(&plists, g_lists);
    cudaGetSymbolAddress(&pwh,    g_wbh);
    cudaGetSymbolAddress(&pwl,    g_wbl);
    cudaGetSymbolAddress(&pdeg,   g_deg);
    cudaGetSymbolAddress(&poff,   g_off);
    cudaGetSymbolAddress(&pcur,   g_cur);
    __nv_bfloat16* wbh = (__nv_bfloat16*)pwh;
    __nv_bfloat16* wbl = (__nv_bfloat16*)pwl;

    constexpr size_t DS128 = 2 * (2 * 5120 + 2 * 128 * 40) * 2;   // 81920 B
    constexpr size_t DS256 = 2 * (2 * 5120 + 2 * 256 * 40) * 2;   // 122880 B

    auto kG   = k_mma<128, 3, false, false, false, 1, false>;
    auto kE1  = k_mma<256, 1, true,  false, true,  2, true>;
    auto kE2  = k_mma<256, 1, false, true,  false, 0, true>;
    auto kGNN = k_mma<128, 2, false, false, false, 1, false>;
    cudaFuncSetAttribute(kG,   cudaFuncAttributeMaxDynamicSharedMemorySize, DS128);
    cudaFuncSetAttribute(kE1,  cudaFuncAttributeMaxDynamicSharedMemorySize, DS256);
    cudaFuncSetAttribute(kE2,  cudaFuncAttributeMaxDynamicSharedMemorySize, DS256);
    cudaFuncSetAttribute(kGNN, cudaFuncAttributeMaxDynamicSharedMemorySize, DS128);

    cudaMemsetAsync(pcnt, 0, sizeof(int) * NEx);
    cudaMemsetAsync(pdeg, 0, sizeof(int) * Nn);

    // 0a) CSR build (one-time; reused by both GNN layers)
    k_hist<<<CDIV(nedges, 256), 256>>>(ei, nedges);
    k_scan<<<1, 1024>>>(Nn);
    cudaMemcpyAsync(pcur, poff, sizeof(int) * Nn, cudaMemcpyDeviceToDevice);
    k_fill<<<CDIV(nedges, 256), 256>>>(ei, nedges);

    // 0b) pre-split weights into [n][k] bf16 hi/lo planes
    k_wprep<<<dim3(CDIV(768 * 128, 256), 1), 256>>>(Wg1,  wbh + OFF_G,  wbl + OFF_G,  768, 128, 768);
    k_wprep<<<dim3(CDIV(256 * 512, 256), NEx), 256>>>(We1, wbh + OFF_E1, wbl + OFF_E1, 256, 512, 256);
    k_wprep<<<dim3(CDIV(512 * 512, 256), NEx), 256>>>(We2, wbh + OFF_E2, wbl + OFF_E2, 512, 512, 512);
    k_wprep<<<dim3(CDIV(512 * 512, 256), 2), 256>>>(Wself, wbh + OFF_GNN,       wbl + OFF_GNN,       512, 512, 1024);
    k_wprep<<<dim3(CDIV(512 * 512, 256), 2), 256>>>(Wnbr,  wbh + OFF_GNN + 512, wbl + OFF_GNN + 512, 512, 512, 1024);

    const int MT = CDIV(Nn, 128);

    // 1) gating hidden: relu([text|tab|str] @ Wg1 + bg1)
    kG<<<dim3(1, MT), 256, DS128>>>(
        text, tab, str, wbh + OFF_G, wbl + OFF_G, bg1, (float*)pghid,
        nullptr, Nn, 3 * Ed, GHd);

    // 2) gating head: softmax top-2, build routing lists + per-node slots
    k_gate<<<CDIV(Nn, 32), 1024>>>(Wg2, bg2);

    // 3) expert MLP layer 1 (gathered rows, gelu), all 5 experts, 128x256 tile
    kE1<<<dim3(Hd / 256, MT, NEx), 256, DS256>>>(
        text, tab, str, wbh + OFF_E1, wbl + OFF_E1, be1, (float*)ph1,
        (const int*)plists, 0, Ed, Hd);

    // 4) expert MLP layer 2 -> dense eout (128x256 tile), then gated combine
    kE2<<<dim3(Hd / 256, MT, NEx), 256, DS256>>>(
        (const float*)ph1, nullptr, nullptr, wbh + OFF_E2, wbl + OFF_E2, be2,
        (float*)peo, (const int*)plists, 0, Hd, Hd);
    k_combine<<<Nn, 128>>>();

    // ---- GNN layer 0: h1 = relu([h | segsum(h)] @ [[Wself0],[Wnbr0]]) ----
    k_gather<<<Nn, 128>>>((const float*)pnf, (float*)pmsg);
    kGNN<<<dim3(Hd / 128, MT), 256, DS128>>>(
        (const float*)pnf, (const float*)pmsg, nullptr,
        wbh + OFF_GNN, wbl + OFF_GNN, nullptr, (float*)phl,
        nullptr, Nn, 2 * Hd, Hd);

    // ---- GNN layer 1 ----
    k_gather<<<Nn, 128>>>((const float*)phl, (float*)pmsg);
    kGNN<<<dim3(Hd / 128, MT), 256, DS128>>>(
        (const float*)phl, (const float*)pmsg, nullptr,
        wbh + OFF_GNN + (size_t)512 * 1024, wbl + OFF_GNN + (size_t)512 * 1024,
        nullptr, out, nullptr, Nn, 2 * Hd, Hd);
}

// round 16
// speedup vs baseline: 1.0195x; 1.0195x over previous
#include <cuda_runtime.h>
#include <cuda_bf16.h>
#include <cstdint>

#define CDIV(a,b) (((a)+(b)-1)/(b))

constexpr int Nn  = 50000;
constexpr int Ed  = 256;
constexpr int Hd  = 512;
constexpr int NEx = 5;
constexpr int GHd = 128;
constexpr int EDGES_MAX = 800000;

// ---------------- scratch (static device globals; no allocation) -------------
__device__ float g_ghid[(size_t)Nn * GHd];
__device__ int   g_lists[NEx * Nn];
__device__ float g_gatew[NEx * Nn];
__device__ int   g_slot[2 * Nn];                    // per-node assignment slots
__device__ int   g_counts[NEx];
__device__ float g_h1[(size_t)NEx * Nn * Hd];
__device__ float g_eout[(size_t)NEx * Nn * Hd];     // dense expert-2 output
__device__ float g_nf[(size_t)Nn * Hd];
__device__ float g_msg[(size_t)Nn * Hd];
__device__ float g_hl[(size_t)Nn * Hd];

// CSR for edge segment-sum
__device__ int g_deg[Nn];
__device__ int g_off[Nn + 1];
__device__ int g_cur[Nn];
__device__ int g_esrc[EDGES_MAX];

// pre-split weights, [n][k] layout, bf16 hi/lo planes
constexpr size_t OFF_G   = 0;                       // 128 x 768
constexpr size_t OFF_E1  = 98304;                   // 5 x 512 x 256
constexpr size_t OFF_E2  = 753664;                  // 5 x 512 x 512
constexpr size_t OFF_GNN = 2064384;                 // 2 x 512 x 1024
constexpr size_t WTOT    = 3112960;
__device__ __nv_bfloat16 g_wbh[WTOT];
__device__ __nv_bfloat16 g_wbl[WTOT];

// ---------------- helpers ----------------------------------------------------
__device__ __forceinline__ float gelu_f(float x) {
    float t = tanhf(0.7978845608028654f * (x + 0.044715f * x * x * x));
    return 0.5f * x * (1.0f + t);
}

__device__ __forceinline__ uint32_t packbf(float lo, float hi) {
    __nv_bfloat162 h = __floats2bfloat162_rn(lo, hi);
    return *reinterpret_cast<uint32_t*>(&h);
}

__device__ __forceinline__ uint32_t smem_u32(const void* p) {
    uint32_t a;
    asm("{ .reg .u64 t; cvta.to.shared.u64 t, %1; cvt.u32.u64 %0, t; }"
        : "=r"(a) : "l"(p));
    return a;
}

__device__ __forceinline__ void mma16816(
    float (&c)[4], const uint32_t (&a)[4], const uint32_t (&b)[2])
{
    asm volatile(
        "mma.sync.aligned.m16n8k16.row.col.f32.bf16.bf16.f32 "
        "{%0,%1,%2,%3}, {%4,%5,%6,%7}, {%8,%9}, {%0,%1,%2,%3};"
        : "+f"(c[0]), "+f"(c[1]), "+f"(c[2]), "+f"(c[3])
        : "r"(a[0]), "r"(a[1]), "r"(a[2]), "r"(a[3]), "r"(b[0]), "r"(b[1]));
}

__device__ __forceinline__ void ldm_x4(uint32_t (&r)[4], uint32_t addr) {
    asm volatile("ldmatrix.sync.aligned.m8n8.x4.shared.b16 {%0,%1,%2,%3}, [%4];"
                 : "=r"(r[0]), "=r"(r[1]), "=r"(r[2]), "=r"(r[3]) : "r"(addr));
}

// ---------------- weight prep: transpose + bf16 hi/lo split ------------------
__global__ void k_wprep(const float* __restrict__ W,
                        __nv_bfloat16* __restrict__ oh,
                        __nv_bfloat16* __restrict__ ol,
                        int Kw, int N, int ldk)
{
    int b = blockIdx.y;
    const float* Wp = W + (size_t)b * Kw * N;
    __nv_bfloat16* ohp = oh + (size_t)b * N * ldk;
    __nv_bfloat16* olp = ol + (size_t)b * N * ldk;
    int idx = blockIdx.x * blockDim.x + threadIdx.x;
    if (idx >= Kw * N) return;
    int k = idx / N, n = idx - k * N;
    float x = Wp[idx];
    __nv_bfloat16 h = __float2bfloat16(x);
    ohp[(size_t)n * ldk + k] = h;
    olp[(size_t)n * ldk + k] = __float2bfloat16(x - __bfloat162float(h));
}

// ---------------- bf16x3 tensor-core GEMM (128x128 tile, BK=32) --------------
constexpr int PB    = 128 * 40 * 2;        // bytes per plane (10240)
constexpr int DSMEM = 8 * PB;              // 2 buffers x 4 planes = 81920

template<int NSRC, bool ESEL, bool AEXP, bool GATHER, int ACT, bool EXPERT>
__global__ void __launch_bounds__(256) k_mma(
    const float* __restrict__ A0, const float* __restrict__ A1,
    const float* __restrict__ A2,
    const __nv_bfloat16* __restrict__ Bh, const __nv_bfloat16* __restrict__ Bl,
    const float* __restrict__ bias, float* __restrict__ C,
    const int* __restrict__ rowlist,
    int Mfixed, int K, int NC)
{
    int M;
    const __nv_bfloat16* Bhp = Bh;
    const __nv_bfloat16* Blp = Bl;
    const float* biasp = bias;
    float*       Cp    = C;
    const int*   rl    = rowlist;
    const float* Asel  = A0;
    if (EXPERT) {
        int e = blockIdx.z;
        M = g_counts[e]; if (M > Nn) M = Nn;
        Bhp = Bh + (size_t)e * (size_t)NC * K;
        Blp = Bl + (size_t)e * (size_t)NC * K;
        if (bias) biasp = bias + (size_t)e * NC;
        if (ESEL) {
            const int map[NEx] = { 1, 2, 0, 0, 2 };  // tab, str, text, text, str
            int s = map[e];
            Asel = (s == 0) ? A0 : ((s == 1) ? A1 : A2);
        }
        if (AEXP) Asel = A0 + (size_t)e * (size_t)Nn * K;
        rl = rowlist + e * Nn;
        Cp = C + (size_t)e * (size_t)Nn * NC;
    } else {
        M = Mfixed;
    }
    if ((int)(blockIdx.y * 128) >= M) return;

    extern __shared__ __nv_bfloat16 sm[];
    const uint32_t smb = smem_u32(sm);

    const int tid  = threadIdx.x;
    const int warp = tid >> 5, lane = tid & 31;
    const int wm = warp >> 2, wn = warp & 3;      // warp tile: 64 x 32
    const int gid = lane >> 2, tig = lane & 3;
    const int row0 = blockIdx.y * 128;
    const int col0 = blockIdx.x * 128;

    // ---- A loader: row am, 16 k-values at ak ----
    const int am = tid >> 1;
    const int ak = (tid & 1) << 4;
    const bool avalid = (row0 + am) < M;
    int arow = row0 + am;
    if (GATHER) {
        arow = avalid ? rl[arow] : 0;
        if ((unsigned)arow >= (unsigned)Nn) arow = 0;
    } else if (!avalid) arow = 0;

    auto aload = [&](int k0, float4 (&d)[4]) {
        if (!avalid) {
            d[0] = d[1] = d[2] = d[3] = make_float4(0.f, 0.f, 0.f, 0.f);
            return;
        }
        int kg = k0 + ak;
        const float* p;
        if (NSRC == 3) {
            const float* s = (kg < 256) ? A0 : ((kg < 512) ? A1 : A2);
            p = s + (size_t)arow * 256 + (kg & 255);
        } else if (NSRC == 2) {
            const float* s = (kg < 512) ? A0 : A1;
            p = s + (size_t)arow * 512 + (kg & 511);
        } else {
            p = Asel + (size_t)arow * (size_t)K + kg;
        }
        #pragma unroll
        for (int q = 0; q < 4; q++) d[q] = *(const float4*)(p + q * 4);
    };

    // ---- B loader: pre-split bf16, [n][k], fully coalesced ----
    const int bn = tid >> 1;
    const int bk = (tid & 1) << 4;
    const __nv_bfloat16* bhrow = Bhp + (size_t)(col0 + bn) * K + bk;
    const __nv_bfloat16* blrow = Blp + (size_t)(col0 + bn) * K + bk;
    auto bload = [&](int k0, uint4 (&dh)[2], uint4 (&dl)[2]) {
        const uint4* ph = (const uint4*)(bhrow + k0);
        const uint4* pl = (const uint4*)(blrow + k0);
        dh[0] = ph[0]; dh[1] = ph[1];
        dl[0] = pl[0]; dl[1] = pl[1];
    };

    // ---- stage regs -> smem (split A into hi/lo, copy B) ----
    auto store = [&](int b, const float4 (&av)[4], const uint4 (&bvh)[2],
                     const uint4 (&bvl)[2]) {
        __nv_bfloat16* base = sm + (size_t)b * (4 * PB / 2);
        uint32_t* ah = (uint32_t*)(base + am * 40 + ak);
        uint32_t* al = (uint32_t*)(base + (PB / 2) + am * 40 + ak);
        #pragma unroll
        for (int q = 0; q < 4; q++) {
            float4 v = av[q];
            uint32_t hp0 = packbf(v.x, v.y);
            uint32_t hp1 = packbf(v.z, v.w);
            __nv_bfloat162 h0 = *reinterpret_cast<__nv_bfloat162*>(&hp0);
            __nv_bfloat162 h1 = *reinterpret_cast<__nv_bfloat162*>(&hp1);
            ah[q * 2]     = hp0;
            ah[q * 2 + 1] = hp1;
            al[q * 2]     = packbf(v.x - __low2float(h0), v.y - __high2float(h0));
            al[q * 2 + 1] = packbf(v.z - __low2float(h1), v.w - __high2float(h1));
        }
        *(uint4*)(base + PB + bn * 40 + bk)            = bvh[0];
        *(uint4*)(base + PB + bn * 40 + bk + 8)        = bvh[1];
        *(uint4*)(base + PB + (PB / 2) + bn * 40 + bk)     = bvl[0];
        *(uint4*)(base + PB + (PB / 2) + bn * 40 + bk + 8) = bvl[1];
    };

    float c[4][4][4];
    #pragma unroll
    for (int i = 0; i < 4; i++)
        #pragma unroll
        for (int j = 0; j < 4; j++)
            #pragma unroll
            for (int q = 0; q < 4; q++) c[i][j][q] = 0.f;

    const int ltr = lane & 7;
    const int lt8 = ((lane >> 3) & 1) * 8;
    const int lk8 = (lane >> 4) * 8;

    auto compute = [&](int b) {
        const uint32_t sbase = smb + (uint32_t)b * 4 * PB;
        #pragma unroll
        for (int ks = 0; ks < 32; ks += 16) {
            uint32_t bfh[4][2], bfl[4][2];
            #pragma unroll
            for (int jp = 0; jp < 2; jp++) {
                int nrow = wn * 32 + (jp * 2 + (lane >> 4)) * 8 + ltr;
                int koff = ks + ((lane >> 3) & 1) * 8;
                uint32_t addr = sbase + 2 * PB + (uint32_t)(nrow * 40 + koff) * 2;
                uint32_t r[4];
                ldm_x4(r, addr);
                bfh[jp*2][0] = r[0]; bfh[jp*2][1] = r[1];
                bfh[jp*2+1][0] = r[2]; bfh[jp*2+1][1] = r[3];
                ldm_x4(r, addr + PB);
                bfl[jp*2][0] = r[0]; bfl[jp*2][1] = r[1];
                bfl[jp*2+1][0] = r[2]; bfl[jp*2+1][1] = r[3];
            }
            #pragma unroll
            for (int mi = 0; mi < 4; mi++) {
                int mrow = wm * 64 + mi * 16 + lt8 + ltr;
                int koff = ks + lk8;
                uint32_t addr = sbase + (uint32_t)(mrow * 40 + koff) * 2;
                uint32_t ah[4], al[4];
                ldm_x4(ah, addr);
                ldm_x4(al, addr + PB);
                #pragma unroll
                for (int nj = 0; nj < 4; nj++) {
                    mma16816(c[mi][nj], ah, bfh[nj]);   // Ah*Bh
                    mma16816(c[mi][nj], ah, bfl[nj]);   // Ah*Bl
                    mma16816(c[mi][nj], al, bfh[nj]);   // Al*Bh
                }
            }
        }
    };

    const int nch = K >> 5;
    float4 apre[4]; uint4 bph[2], bpl[2];
    aload(0, apre); bload(0, bph, bpl);
    store(0, apre, bph, bpl);
    __syncthreads();

    for (int ch = 0; ch < nch; ch++) {
        if (ch + 1 < nch) { aload((ch + 1) << 5, apre); bload((ch + 1) << 5, bph, bpl); }
        compute(ch & 1);
        if (ch + 1 < nch) {
            store((ch + 1) & 1, apre, bph, bpl);
            __syncthreads();
        }
    }

    // ---- epilogue: dense float2 stores ----
    #pragma unroll
    for (int mi = 0; mi < 4; mi++) {
        #pragma unroll
        for (int h = 0; h < 2; h++) {
            int rg = row0 + wm * 64 + mi * 16 + gid + h * 8;
            if (rg >= M) continue;
            #pragma unroll
            for (int nj = 0; nj < 4; nj++) {
                int col = col0 + wn * 32 + nj * 8 + tig * 2;
                float vx = c[mi][nj][h * 2 + 0];
                float vy = c[mi][nj][h * 2 + 1];
                if (biasp) { vx += biasp[col]; vy += biasp[col + 1]; }
                if (ACT == 1) { vx = fmaxf(vx, 0.f); vy = fmaxf(vy, 0.f); }
                else if (ACT == 2) { vx = gelu_f(vx); vy = gelu_f(vy); }
                *(float2*)(Cp + (size_t)rg * NC + col) = make_float2(vx, vy);
            }
        }
    }
}

// ---------------- gating head: logits -> top2 -> routing lists + slots -------
__global__ void k_gate(const float* __restrict__ Wg2, const float* __restrict__ bg2) {
    __shared__ int   scnt[NEx], sbase[NEx];
    __shared__ int   se[64];
    __shared__ int   snode[64];
    __shared__ int   spos[64];
    __shared__ float sg[64];

    const int tid = threadIdx.x;
    if (tid < NEx) scnt[tid] = 0;
    __syncthreads();

    const int warp = tid >> 5, lane = tid & 31;
    const int node = blockIdx.x * 32 + warp;

    if (node < Nn) {
        const float* gr = g_ghid + (size_t)node * GHd;
        float v0 = gr[lane], v1 = gr[lane + 32], v2 = gr[lane + 64], v3 = gr[lane + 96];
        float l[NEx];
        #pragma unroll
        for (int e = 0; e < NEx; e++) {
            float p = v0 * Wg2[lane * NEx + e]
                    + v1 * Wg2[(lane + 32) * NEx + e]
                    + v2 * Wg2[(lane + 64) * NEx + e]
                    + v3 * Wg2[(lane + 96) * NEx + e];
            #pragma unroll
            for (int off = 16; off > 0; off >>= 1)
                p += __shfl_xor_sync(0xffffffffu, p, off);
            l[e] = p;
        }
        if (lane == 0) {
            #pragma unroll
            for (int e = 0; e < NEx; e++) l[e] += bg2[e];
            int e0 = 0;
            #pragma unroll
            for (int e = 1; e < NEx; e++) if (l[e] > l[e0]) e0 = e;
            int e1 = -1;
            #pragma unroll
            for (int e = 0; e < NEx; e++)
                if (e != e0 && (e1 < 0 || l[e] > l[e1])) e1 = e;
            float gate0 = 1.f / (1.f + expf(l[e1] - l[e0]));
            float gate1 = 1.f - gate0;
            int s0 = warp * 2, s1 = warp * 2 + 1;
            se[s0] = e0; snode[s0] = node; sg[s0] = gate0;
            spos[s0] = atomicAdd(&scnt[e0], 1);
            se[s1] = e1; snode[s1] = node; sg[s1] = gate1;
            spos[s1] = atomicAdd(&scnt[e1], 1);
        }
    } else if (lane == 0) {
        se[warp * 2] = -1; se[warp * 2 + 1] = -1;
    }
    __syncthreads();
    if (tid < NEx) sbase[tid] = atomicAdd(&g_counts[tid], scnt[tid]);
    __syncthreads();
    if (tid < 64 && se[tid] >= 0) {
        int e = se[tid];
        int p = sbase[e] + spos[tid];
        if (p >= 0 && p < Nn) {
            g_lists[e * Nn + p] = snode[tid];
            g_gatew[e * Nn + p] = sg[tid];
            g_slot[snode[tid] * 2 + (tid & 1)] = e * Nn + p;
        }
    }
}

// ---------------- combine: nf[n] = g0*eout[slot0] + g1*eout[slot1] -----------
__global__ void __launch_bounds__(128) k_combine() {
    const int n = blockIdx.x;
    const int t = threadIdx.x;            // float4 lane, 128 per row
    int s0 = g_slot[n * 2], s1 = g_slot[n * 2 + 1];
    if ((unsigned)s0 >= (unsigned)(NEx * Nn)) s0 = 0;
    if ((unsigned)s1 >= (unsigned)(NEx * Nn)) s1 = 0;
    float g0 = g_gatew[s0], g1 = g_gatew[s1];
    float4 a = ((const float4*)(g_eout + (size_t)s0 * Hd))[t];
    float4 b = ((const float4*)(g_eout + (size_t)s1 * Hd))[t];
    float4 r;
    r.x = g0 * a.x + g1 * b.x;
    r.y = g0 * a.y + g1 * b.y;
    r.z = g0 * a.z + g1 * b.z;
    r.w = g0 * a.w + g1 * b.w;
    ((float4*)(g_nf + (size_t)n * Hd))[t] = r;
}

// ---------------- CSR build: hist -> scan -> fill -----------------------------
__global__ void k_hist(const int* __restrict__ ei, int nedges) {
    int e = blockIdx.x * blockDim.x + threadIdx.x;
    if (e >= nedges) return;
    int d = ei[nedges + e];
    if ((unsigned)d < (unsigned)Nn) atomicAdd(&g_deg[d], 1);
}

// single-block chunked exclusive scan; writes BOTH g_off and g_cur
__global__ void k_scan(int n) {
    __shared__ int sw[32];
    __shared__ int scarry;
    const int tid = threadIdx.x;
    const int lane = tid & 31, warp = tid >> 5;
    if (tid == 0) scarry = 0;
    __syncthreads();
    for (int base = 0; base < n; base += 1024) {
        int i = base + tid;
        int v = (i < n) ? g_deg[i] : 0;
        int x = v;
        #pragma unroll
        for (int o = 1; o < 32; o <<= 1) {
            int y = __shfl_up_sync(0xffffffffu, x, o);
            if (lane >= o) x += y;
        }
        if (lane == 31) sw[warp] = x;
        __syncthreads();
        if (warp == 0) {
            int s = sw[lane];
            #pragma unroll
            for (int o = 1; o < 32; o <<= 1) {
                int y = __shfl_up_sync(0xffffffffu, s, o);
                if (lane >= o) s += y;
            }
            sw[lane] = s;
        }
        __syncthreads();
        int incl  = x + (warp ? sw[warp - 1] : 0);
        int carry = scarry;
        if (i < n) {
            int excl = carry + incl - v;
            g_off[i] = excl;
            g_cur[i] = excl;
        }
        int total = sw[31];
        __syncthreads();
        if (tid == 0) scarry = carry + total;
        __syncthreads();
    }
    if (tid == 0) g_off[n] = scarry;
}

__global__ void k_fill(const int* __restrict__ ei, int nedges) {
    int e = blockIdx.x * blockDim.x + threadIdx.x;
    if (e >= nedges) return;
    int s = ei[e];
    int d = ei[nedges + e];
    if ((unsigned)s >= (unsigned)Nn || (unsigned)d >= (unsigned)Nn) return;
    int pos = atomicAdd(&g_cur[d], 1);
    if ((unsigned)pos < (unsigned)EDGES_MAX) g_esrc[pos] = s;
}

// ---------------- CSR gather: msg[d] = sum_{e: dst=d} h[src[e]] ---------------
// 256 threads = 2 nodes per block (128 float4 lanes per node)
__global__ void __launch_bounds__(256) k_gather(
    const float* __restrict__ h, float* __restrict__ msg)
{
    const int d = blockIdx.x * 2 + (threadIdx.x >> 7);
    const int t = threadIdx.x & 127;      // float4 lane within row
    if (d >= Nn) return;
    int beg = g_off[d], end = g_off[d + 1];
    float4 acc = make_float4(0.f, 0.f, 0.f, 0.f);
    int i = beg;
    for (; i + 3 < end; i += 4) {
        int s0 = g_esrc[i],     s1 = g_esrc[i + 1];
        int s2 = g_esrc[i + 2], s3 = g_esrc[i + 3];
        float4 v0 = ((const float4*)(h + (size_t)s0 * Hd))[t];
        float4 v1 = ((const float4*)(h + (size_t)s1 * Hd))[t];
        float4 v2 = ((const float4*)(h + (size_t)s2 * Hd))[t];
        float4 v3 = ((const float4*)(h + (size_t)s3 * Hd))[t];
        acc.x += (v0.x + v1.x) + (v2.x + v3.x);
        acc.y += (v0.y + v1.y) + (v2.y + v3.y);
        acc.z += (v0.z + v1.z) + (v2.z + v3.z);
        acc.w += (v0.w + v1.w) + (v2.w + v3.w);
    }
    for (; i < end; i++) {
        int s0 = g_esrc[i];
        float4 v0 = ((const float4*)(h + (size_t)s0 * Hd))[t];
        acc.x += v0.x; acc.y += v0.y; acc.z += v0.z; acc.w += v0.w;
    }
    ((float4*)(msg + (size_t)d * Hd))[t] = acc;
}

// ---------------- launch -----------------------------------------------------
extern "C" void kernel_launch(void* const* d_in, const int* in_sizes, int n_in,
                              void* d_out, int out_size)
{
    const float* text = (const float*)d_in[0];
    const float* tab  = (const float*)d_in[1];
    const float* str  = (const float*)d_in[2];
    const int*   ei   = (const int*)d_in[3];
    const float* Wg1  = (const float*)d_in[4];
    const float* bg1  = (const float*)d_in[5];
    const float* Wg2  = (const float*)d_in[6];
    const float* bg2  = (const float*)d_in[7];
    const float* We1  = (const float*)d_in[8];
    const float* be1  = (const float*)d_in[9];
    const float* We2  = (const float*)d_in[10];
    const float* be2  = (const float*)d_in[11];
    const float* Wself = (const float*)d_in[12];
    const float* Wnbr  = (const float*)d_in[13];
    float* out = (float*)d_out;
    const int nedges = in_sizes[3] / 2;

    void *pcnt, *pghid, *pnf, *pmsg, *phl, *ph1, *peo, *plists, *pwh, *pwl;
    void *pdeg;
    cudaGetSymbolAddress(&pcnt,   g_counts);
    cudaGetSymbolAddress(&pghid,  g_ghid);
    cudaGetSymbolAddress(&pnf,    g_nf);
    cudaGetSymbolAddress(&pmsg,   g_msg);
    cudaGetSymbolAddress(&phl,    g_hl);
    cudaGetSymbolAddress(&ph1,    g_h1);
    cudaGetSymbolAddress(&peo,    g_eout);
    cudaGetSymbolAddress(&plists, g_lists);
    cudaGetSymbolAddress(&pwh,    g_wbh);
    cudaGetSymbolAddress(&pwl,    g_wbl);
    cudaGetSymbolAddress(&pdeg,   g_deg);
    __nv_bfloat16* wbh = (__nv_bfloat16*)pwh;
    __nv_bfloat16* wbl = (__nv_bfloat16*)pwl;

    auto kG   = k_mma<3, false, false, false, 1, false>;
    auto kE1  = k_mma<1, true,  false, true,  2, true>;
    auto kE2  = k_mma<1, false, true,  false, 0, true>;
    auto kGNN = k_mma<2, false, false, false, 1, false>;
    cudaFuncSetAttribute(kG,   cudaFuncAttributeMaxDynamicSharedMemorySize, DSMEM);
    cudaFuncSetAttribute(kE1,  cudaFuncAttributeMaxDynamicSharedMemorySize, DSMEM);
    cudaFuncSetAttribute(kE2,  cudaFuncAttributeMaxDynamicSharedMemorySize, DSMEM);
    cudaFuncSetAttribute(kGNN, cudaFuncAttributeMaxDynamicSharedMemorySize, DSMEM);

    cudaMemsetAsync(pcnt, 0, sizeof(int) * NEx);
    cudaMemsetAsync(pdeg, 0, sizeof(int) * Nn);

    // 0a) CSR build (one-time; reused by both GNN layers)
    k_hist<<<CDIV(nedges, 256), 256>>>(ei, nedges);
    k_scan<<<1, 1024>>>(Nn);
    k_fill<<<CDIV(nedges, 256), 256>>>(ei, nedges);

    // 0b) pre-split weights into [n][k] bf16 hi/lo planes
    k_wprep<<<dim3(CDIV(768 * 128, 256), 1), 256>>>(Wg1,  wbh + OFF_G,  wbl + OFF_G,  768, 128, 768);
    k_wprep<<<dim3(CDIV(256 * 512, 256), NEx), 256>>>(We1, wbh + OFF_E1, wbl + OFF_E1, 256, 512, 256);
    k_wprep<<<dim3(CDIV(512 * 512, 256), NEx), 256>>>(We2, wbh + OFF_E2, wbl + OFF_E2, 512, 512, 512);
    k_wprep<<<dim3(CDIV(512 * 512, 256), 2), 256>>>(Wself, wbh + OFF_GNN,       wbl + OFF_GNN,       512, 512, 1024);
    k_wprep<<<dim3(CDIV(512 * 512, 256), 2), 256>>>(Wnbr,  wbh + OFF_GNN + 512, wbl + OFF_GNN + 512, 512, 512, 1024);

    const int MT = CDIV(Nn, 128);

    // 1) gating hidden: relu([text|tab|str] @ Wg1 + bg1)
    kG<<<dim3(1, MT), 256, DSMEM>>>(
        text, tab, str, wbh + OFF_G, wbl + OFF_G, bg1, (float*)pghid,
        nullptr, Nn, 3 * Ed, GHd);

    // 2) gating head: softmax top-2, build routing lists + per-node slots
    k_gate<<<CDIV(Nn, 32), 1024>>>(Wg2, bg2);

    // 3) expert MLP layer 1 (gathered rows, gelu), all 5 experts
    kE1<<<dim3(Hd / 128, MT, NEx), 256, DSMEM>>>(
        text, tab, str, wbh + OFF_E1, wbl + OFF_E1, be1, (float*)ph1,
        (const int*)plists, 0, Ed, Hd);

    // 4) expert MLP layer 2 -> dense eout, then per-node gated combine
    kE2<<<dim3(Hd / 128, MT, NEx), 256, DSMEM>>>(
        (const float*)ph1, nullptr, nullptr, wbh + OFF_E2, wbl + OFF_E2, be2,
        (float*)peo, (const int*)plists, 0, Hd, Hd);
    k_combine<<<Nn, 128>>>();

    // ---- GNN layer 0: h1 = relu([h | segsum(h)] @ [[Wself0],[Wnbr0]]) ----
    k_gather<<<CDIV(Nn, 2), 256>>>((const float*)pnf, (float*)pmsg);
    kGNN<<<dim3(Hd / 128, MT), 256, DSMEM>>>(
        (const float*)pnf, (const float*)pmsg, nullptr,
        wbh + OFF_GNN, wbl + OFF_GNN, nullptr, (float*)phl,
        nullptr, Nn, 2 * Hd, Hd);

    // ---- GNN layer 1 ----
    k_gather<<<CDIV(Nn, 2), 256>>>((const float*)phl, (float*)pmsg);
    kGNN<<<dim3(Hd / 128, MT), 256, DSMEM>>>(
        (const float*)phl, (const float*)pmsg, nullptr,
        wbh + OFF_GNN + (size_t)512 * 1024, wbl + OFF_GNN + (size_t)512 * 1024,
        nullptr, out, nullptr, Nn, 2 * Hd, Hd);
}

// round 17
// speedup vs baseline: 1.0360x; 1.0161x over previous
#include <cuda_runtime.h>
#include <cuda_bf16.h>
#include <cstdint>

#define CDIV(a,b) (((a)+(b)-1)/(b))

constexpr int Nn  = 50000;
constexpr int Ed  = 256;
constexpr int Hd  = 512;
constexpr int NEx = 5;
constexpr int GHd = 128;
constexpr int EDGES_MAX = 800000;

// ---------------- scratch (static device globals; no allocation) -------------
__device__ float g_ghid[(size_t)Nn * GHd];
__device__ int   g_lists[NEx * Nn];
__device__ float g_gatew[NEx * Nn];
__device__ int   g_slot[2 * Nn];                    // per-node assignment slots
__device__ int   g_counts[NEx];
__device__ float g_h1[(size_t)NEx * Nn * Hd];
__device__ float g_eout[(size_t)NEx * Nn * Hd];     // dense expert-2 output
__device__ float g_nf[(size_t)Nn * Hd];
__device__ float g_msg[(size_t)Nn * Hd];
__device__ float g_hl[(size_t)Nn * Hd];

// CSR for edge segment-sum
__device__ int g_deg[Nn];
__device__ int g_off[Nn + 1];
__device__ int g_cur[Nn];
__device__ int g_esrc[EDGES_MAX];

// pre-split weights, [n][k] layout, bf16 hi/lo planes
constexpr size_t OFF_G   = 0;                       // 128 x 768
constexpr size_t OFF_E1  = 98304;                   // 5 x 512 x 256
constexpr size_t OFF_E2  = 753664;                  // 5 x 512 x 512
constexpr size_t OFF_GNN = 2064384;                 // 2 x 512 x 1024
constexpr size_t WTOT    = 3112960;
__device__ __nv_bfloat16 g_wbh[WTOT];
__device__ __nv_bfloat16 g_wbl[WTOT];

// ---------------- helpers ----------------------------------------------------
__device__ __forceinline__ float gelu_f(float x) {
    float t = tanhf(0.7978845608028654f * (x + 0.044715f * x * x * x));
    return 0.5f * x * (1.0f + t);
}

__device__ __forceinline__ uint32_t packbf(float lo, float hi) {
    __nv_bfloat162 h = __floats2bfloat162_rn(lo, hi);
    return *reinterpret_cast<uint32_t*>(&h);
}

__device__ __forceinline__ uint32_t smem_u32(const void* p) {
    uint32_t a;
    asm("{ .reg .u64 t; cvta.to.shared.u64 t, %1; cvt.u32.u64 %0, t; }"
        : "=r"(a) : "l"(p));
    return a;
}

__device__ __forceinline__ void mma16816(
    float (&c)[4], const uint32_t (&a)[4], const uint32_t (&b)[2])
{
    asm volatile(
        "mma.sync.aligned.m16n8k16.row.col.f32.bf16.bf16.f32 "
        "{%0,%1,%2,%3}, {%4,%5,%6,%7}, {%8,%9}, {%0,%1,%2,%3};"
        : "+f"(c[0]), "+f"(c[1]), "+f"(c[2]), "+f"(c[3])
        : "r"(a[0]), "r"(a[1]), "r"(a[2]), "r"(a[3]), "r"(b[0]), "r"(b[1]));
}

__device__ __forceinline__ void ldm_x4(uint32_t (&r)[4], uint32_t addr) {
    asm volatile("ldmatrix.sync.aligned.m8n8.x4.shared.b16 {%0,%1,%2,%3}, [%4];"
                 : "=r"(r[0]), "=r"(r[1]), "=r"(r[2]), "=r"(r[3]) : "r"(addr));
}

// ---------------- weight prep: transpose + bf16 hi/lo split ------------------
__global__ void k_wprep(const float* __restrict__ W,
                        __nv_bfloat16* __restrict__ oh,
                        __nv_bfloat16* __restrict__ ol,
                        int Kw, int N, int ldk)
{
    int b = blockIdx.y;
    const float* Wp = W + (size_t)b * Kw * N;
    __nv_bfloat16* ohp = oh + (size_t)b * N * ldk;
    __nv_bfloat16* olp = ol + (size_t)b * N * ldk;
    int idx = blockIdx.x * blockDim.x + threadIdx.x;
    if (idx >= Kw * N) return;
    int k = idx / N, n = idx - k * N;
    float x = Wp[idx];
    __nv_bfloat16 h = __float2bfloat16(x);
    ohp[(size_t)n * ldk + k] = h;
    olp[(size_t)n * ldk + k] = __float2bfloat16(x - __bfloat162float(h));
}

// ---------------- bf16x3 tensor-core GEMM (128x128 tile, BK=32) --------------
constexpr int PB    = 128 * 40 * 2;        // bytes per plane (10240)
constexpr int DSMEM = 8 * PB;              // 2 buffers x 4 planes = 81920

template<int NSRC, bool ESEL, bool AEXP, bool GATHER, int ACT, bool EXPERT>
__global__ void __launch_bounds__(256) k_mma(
    const float* __restrict__ A0, const float* __restrict__ A1,
    const float* __restrict__ A2,
    const __nv_bfloat16* __restrict__ Bh, const __nv_bfloat16* __restrict__ Bl,
    const float* __restrict__ bias, float* __restrict__ C,
    const int* __restrict__ rowlist,
    int Mfixed, int K, int NC)
{
    int M;
    const __nv_bfloat16* Bhp = Bh;
    const __nv_bfloat16* Blp = Bl;
    const float* biasp = bias;
    float*       Cp    = C;
    const int*   rl    = rowlist;
    const float* Asel  = A0;
    if (EXPERT) {
        int e = blockIdx.z;
        M = g_counts[e]; if (M > Nn) M = Nn;
        Bhp = Bh + (size_t)e * (size_t)NC * K;
        Blp = Bl + (size_t)e * (size_t)NC * K;
        if (bias) biasp = bias + (size_t)e * NC;
        if (ESEL) {
            const int map[NEx] = { 1, 2, 0, 0, 2 };  // tab, str, text, text, str
            int s = map[e];
            Asel = (s == 0) ? A0 : ((s == 1) ? A1 : A2);
        }
        if (AEXP) Asel = A0 + (size_t)e * (size_t)Nn * K;
        rl = rowlist + e * Nn;
        Cp = C + (size_t)e * (size_t)Nn * NC;
    } else {
        M = Mfixed;
    }
    if ((int)(blockIdx.y * 128) >= M) return;

    extern __shared__ __nv_bfloat16 sm[];
    const uint32_t smb = smem_u32(sm);

    const int tid  = threadIdx.x;
    const int warp = tid >> 5, lane = tid & 31;
    const int wm = warp >> 2, wn = warp & 3;      // warp tile: 64 x 32
    const int gid = lane >> 2, tig = lane & 3;
    const int row0 = blockIdx.y * 128;
    const int col0 = blockIdx.x * 128;

    // ---- A loader: row am, 16 k-values at ak ----
    const int am = tid >> 1;
    const int ak = (tid & 1) << 4;
    const bool avalid = (row0 + am) < M;
    int arow = row0 + am;
    if (GATHER) {
        arow = avalid ? rl[arow] : 0;
        if ((unsigned)arow >= (unsigned)Nn) arow = 0;
    } else if (!avalid) arow = 0;

    auto aload = [&](int k0, float4 (&d)[4]) {
        if (!avalid) {
            d[0] = d[1] = d[2] = d[3] = make_float4(0.f, 0.f, 0.f, 0.f);
            return;
        }
        int kg = k0 + ak;
        const float* p;
        if (NSRC == 3) {
            const float* s = (kg < 256) ? A0 : ((kg < 512) ? A1 : A2);
            p = s + (size_t)arow * 256 + (kg & 255);
        } else if (NSRC == 2) {
            const float* s = (kg < 512) ? A0 : A1;
            p = s + (size_t)arow * 512 + (kg & 511);
        } else {
            p = Asel + (size_t)arow * (size_t)K + kg;
        }
        #pragma unroll
        for (int q = 0; q < 4; q++) d[q] = *(const float4*)(p + q * 4);
    };

    // ---- B loader: pre-split bf16, [n][k], fully coalesced ----
    const int bn = tid >> 1;
    const int bk = (tid & 1) << 4;
    const __nv_bfloat16* bhrow = Bhp + (size_t)(col0 + bn) * K + bk;
    const __nv_bfloat16* blrow = Blp + (size_t)(col0 + bn) * K + bk;
    auto bload = [&](int k0, uint4 (&dh)[2], uint4 (&dl)[2]) {
        const uint4* ph = (const uint4*)(bhrow + k0);
        const uint4* pl = (const uint4*)(blrow + k0);
        dh[0] = ph[0]; dh[1] = ph[1];
        dl[0] = pl[0]; dl[1] = pl[1];
    };

    // ---- stage regs -> smem (split A into hi/lo, copy B) ----
    auto store = [&](int b, const float4 (&av)[4], const uint4 (&bvh)[2],
                     const uint4 (&bvl)[2]) {
        __nv_bfloat16* base = sm + (size_t)b * (4 * PB / 2);
        uint32_t* ah = (uint32_t*)(base + am * 40 + ak);
        uint32_t* al = (uint32_t*)(base + (PB / 2) + am * 40 + ak);
        #pragma unroll
        for (int q = 0; q < 4; q++) {
            float4 v = av[q];
            uint32_t hp0 = packbf(v.x, v.y);
            uint32_t hp1 = packbf(v.z, v.w);
            __nv_bfloat162 h0 = *reinterpret_cast<__nv_bfloat162*>(&hp0);
            __nv_bfloat162 h1 = *reinterpret_cast<__nv_bfloat162*>(&hp1);
            ah[q * 2]     = hp0;
            ah[q * 2 + 1] = hp1;
            al[q * 2]     = packbf(v.x - __low2float(h0), v.y - __high2float(h0));
            al[q * 2 + 1] = packbf(v.z - __low2float(h1), v.w - __high2float(h1));
        }
        *(uint4*)(base + PB + bn * 40 + bk)            = bvh[0];
        *(uint4*)(base + PB + bn * 40 + bk + 8)        = bvh[1];
        *(uint4*)(base + PB + (PB / 2) + bn * 40 + bk)     = bvl[0];
        *(uint4*)(base + PB + (PB / 2) + bn * 40 + bk + 8) = bvl[1];
    };

    float c[4][4][4];
    #pragma unroll
    for (int i = 0; i < 4; i++)
        #pragma unroll
        for (int j = 0; j < 4; j++)
            #pragma unroll
            for (int q = 0; q < 4; q++) c[i][j][q] = 0.f;

    const int ltr = lane & 7;
    const int lt8 = ((lane >> 3) & 1) * 8;
    const int lk8 = (lane >> 4) * 8;

    auto compute = [&](int b) {
        const uint32_t sbase = smb + (uint32_t)b * 4 * PB;
        #pragma unroll
        for (int ks = 0; ks < 32; ks += 16) {
            uint32_t bfh[4][2], bfl[4][2];
            #pragma unroll
            for (int jp = 0; jp < 2; jp++) {
                int nrow = wn * 32 + (jp * 2 + (lane >> 4)) * 8 + ltr;
                int koff = ks + ((lane >> 3) & 1) * 8;
                uint32_t addr = sbase + 2 * PB + (uint32_t)(nrow * 40 + koff) * 2;
                uint32_t r[4];
                ldm_x4(r, addr);
                bfh[jp*2][0] = r[0]; bfh[jp*2][1] = r[1];
                bfh[jp*2+1][0] = r[2]; bfh[jp*2+1][1] = r[3];
                ldm_x4(r, addr + PB);
                bfl[jp*2][0] = r[0]; bfl[jp*2][1] = r[1];
                bfl[jp*2+1][0] = r[2]; bfl[jp*2+1][1] = r[3];
            }
            #pragma unroll
            for (int mi = 0; mi < 4; mi++) {
                int mrow = wm * 64 + mi * 16 + lt8 + ltr;
                int koff = ks + lk8;
                uint32_t addr = sbase + (uint32_t)(mrow * 40 + koff) * 2;
                uint32_t ah[4], al[4];
                ldm_x4(ah, addr);
                ldm_x4(al, addr + PB);
                #pragma unroll
                for (int nj = 0; nj < 4; nj++) {
                    mma16816(c[mi][nj], ah, bfh[nj]);   // Ah*Bh
                    mma16816(c[mi][nj], ah, bfl[nj]);   // Ah*Bl
                    mma16816(c[mi][nj], al, bfh[nj]);   // Al*Bh
                }
            }
        }
    };

    const int nch = K >> 5;
    float4 apre[4]; uint4 bph[2], bpl[2];
    aload(0, apre); bload(0, bph, bpl);
    store(0, apre, bph, bpl);
    __syncthreads();

    for (int ch = 0; ch < nch; ch++) {
        if (ch + 1 < nch) { aload((ch + 1) << 5, apre); bload((ch + 1) << 5, bph, bpl); }
        compute(ch & 1);
        if (ch + 1 < nch) {
            store((ch + 1) & 1, apre, bph, bpl);
            __syncthreads();
        }
    }

    // ---- epilogue: dense float2 stores ----
    #pragma unroll
    for (int mi = 0; mi < 4; mi++) {
        #pragma unroll
        for (int h = 0; h < 2; h++) {
            int rg = row0 + wm * 64 + mi * 16 + gid + h * 8;
            if (rg >= M) continue;
            #pragma unroll
            for (int nj = 0; nj < 4; nj++) {
                int col = col0 + wn * 32 + nj * 8 + tig * 2;
                float vx = c[mi][nj][h * 2 + 0];
                float vy = c[mi][nj][h * 2 + 1];
                if (biasp) { vx += biasp[col]; vy += biasp[col + 1]; }
                if (ACT == 1) { vx = fmaxf(vx, 0.f); vy = fmaxf(vy, 0.f); }
                else if (ACT == 2) { vx = gelu_f(vx); vy = gelu_f(vy); }
                *(float2*)(Cp + (size_t)rg * NC + col) = make_float2(vx, vy);
            }
        }
    }
}

// ---------------- gating head: logits -> top2 -> routing lists + slots -------
__global__ void k_gate(const float* __restrict__ Wg2, const float* __restrict__ bg2) {
    __shared__ int   scnt[NEx], sbase[NEx];
    __shared__ int   se[64];
    __shared__ int   snode[64];
    __shared__ int   spos[64];
    __shared__ float sg[64];

    const int tid = threadIdx.x;
    if (tid < NEx) scnt[tid] = 0;
    __syncthreads();

    const int warp = tid >> 5, lane = tid & 31;
    const int node = blockIdx.x * 32 + warp;

    if (node < Nn) {
        const float* gr = g_ghid + (size_t)node * GHd;
        float v0 = gr[lane], v1 = gr[lane + 32], v2 = gr[lane + 64], v3 = gr[lane + 96];
        float l[NEx];
        #pragma unroll
        for (int e = 0; e < NEx; e++) {
            float p = v0 * Wg2[lane * NEx + e]
                    + v1 * Wg2[(lane + 32) * NEx + e]
                    + v2 * Wg2[(lane + 64) * NEx + e]
                    + v3 * Wg2[(lane + 96) * NEx + e];
            #pragma unroll
            for (int off = 16; off > 0; off >>= 1)
                p += __shfl_xor_sync(0xffffffffu, p, off);
            l[e] = p;
        }
        if (lane == 0) {
            #pragma unroll
            for (int e = 0; e < NEx; e++) l[e] += bg2[e];
            int e0 = 0;
            #pragma unroll
            for (int e = 1; e < NEx; e++) if (l[e] > l[e0]) e0 = e;
            int e1 = -1;
            #pragma unroll
            for (int e = 0; e < NEx; e++)
                if (e != e0 && (e1 < 0 || l[e] > l[e1])) e1 = e;
            float gate0 = 1.f / (1.f + expf(l[e1] - l[e0]));
            float gate1 = 1.f - gate0;
            int s0 = warp * 2, s1 = warp * 2 + 1;
            se[s0] = e0; snode[s0] = node; sg[s0] = gate0;
            spos[s0] = atomicAdd(&scnt[e0], 1);
            se[s1] = e1; snode[s1] = node; sg[s1] = gate1;
            spos[s1] = atomicAdd(&scnt[e1], 1);
        }
    } else if (lane == 0) {
        se[warp * 2] = -1; se[warp * 2 + 1] = -1;
    }
    __syncthreads();
    if (tid < NEx) sbase[tid] = atomicAdd(&g_counts[tid], scnt[tid]);
    __syncthreads();
    if (tid < 64 && se[tid] >= 0) {
        int e = se[tid];
        int p = sbase[e] + spos[tid];
        if (p >= 0 && p < Nn) {
            g_lists[e * Nn + p] = snode[tid];
            g_gatew[e * Nn + p] = sg[tid];
            g_slot[snode[tid] * 2 + (tid & 1)] = e * Nn + p;
        }
    }
}

// ---------------- combine: nf[n] = g0*eout[slot0] + g1*eout[slot1] -----------
__global__ void __launch_bounds__(128) k_combine() {
    const int n = blockIdx.x;
    const int t = threadIdx.x;            // float4 lane, 128 per row
    int s0 = g_slot[n * 2], s1 = g_slot[n * 2 + 1];
    if ((unsigned)s0 >= (unsigned)(NEx * Nn)) s0 = 0;
    if ((unsigned)s1 >= (unsigned)(NEx * Nn)) s1 = 0;
    float g0 = g_gatew[s0], g1 = g_gatew[s1];
    float4 a = ((const float4*)(g_eout + (size_t)s0 * Hd))[t];
    float4 b = ((const float4*)(g_eout + (size_t)s1 * Hd))[t];
    float4 r;
    r.x = g0 * a.x + g1 * b.x;
    r.y = g0 * a.y + g1 * b.y;
    r.z = g0 * a.z + g1 * b.z;
    r.w = g0 * a.w + g1 * b.w;
    ((float4*)(g_nf + (size_t)n * Hd))[t] = r;
}

// ---------------- CSR build: hist -> scan -> fill -----------------------------
__global__ void k_hist(const int* __restrict__ ei, int nedges) {
    int e = blockIdx.x * blockDim.x + threadIdx.x;
    if (e >= nedges) return;
    int d = ei[nedges + e];
    if ((unsigned)d < (unsigned)Nn) atomicAdd(&g_deg[d], 1);
}

// single-block chunked exclusive scan; writes BOTH g_off and g_cur
__global__ void k_scan(int n) {
    __shared__ int sw[32];
    __shared__ int scarry;
    const int tid = threadIdx.x;
    const int lane = tid & 31, warp = tid >> 5;
    if (tid == 0) scarry = 0;
    __syncthreads();
    for (int base = 0; base < n; base += 1024) {
        int i = base + tid;
        int v = (i < n) ? g_deg[i] : 0;
        int x = v;
        #pragma unroll
        for (int o = 1; o < 32; o <<= 1) {
            int y = __shfl_up_sync(0xffffffffu, x, o);
            if (lane >= o) x += y;
        }
        if (lane == 31) sw[warp] = x;
        __syncthreads();
        if (warp == 0) {
            int s = sw[lane];
            #pragma unroll
            for (int o = 1; o < 32; o <<= 1) {
                int y = __shfl_up_sync(0xffffffffu, s, o);
                if (lane >= o) s += y;
            }
            sw[lane] = s;
        }
        __syncthreads();
        int incl  = x + (warp ? sw[warp - 1] : 0);
        int carry = scarry;
        if (i < n) {
            int excl = carry + incl - v;
            g_off[i] = excl;
            g_cur[i] = excl;
        }
        int total = sw[31];
        __syncthreads();
        if (tid == 0) scarry = carry + total;
        __syncthreads();
    }
    if (tid == 0) g_off[n] = scarry;
}

__global__ void k_fill(const int* __restrict__ ei, int nedges) {
    int e = blockIdx.x * blockDim.x + threadIdx.x;
    if (e >= nedges) return;
    int s = ei[e];
    int d = ei[nedges + e];
    if ((unsigned)s >= (unsigned)Nn || (unsigned)d >= (unsigned)Nn) return;
    int pos = atomicAdd(&g_cur[d], 1);
    if ((unsigned)pos < (unsigned)EDGES_MAX) g_esrc[pos] = s;
}

// ---------------- CSR gather: msg[d] = sum_{e: dst=d} h[src[e]] ---------------
// 256 threads = 2 nodes per block (128 float4 lanes per node)
__global__ void __launch_bounds__(256) k_gather(
    const float* __restrict__ h, float* __restrict__ msg)
{
    const int d = blockIdx.x * 2 + (threadIdx.x >> 7);
    const int t = threadIdx.x & 127;      // float4 lane within row
    if (d >= Nn) return;
    int beg = g_off[d], end = g_off[d + 1];
    float4 acc = make_float4(0.f, 0.f, 0.f, 0.f);
    int i = beg;
    for (; i + 3 < end; i += 4) {
        int s0 = g_esrc[i],     s1 = g_esrc[i + 1];
        int s2 = g_esrc[i + 2], s3 = g_esrc[i + 3];
        float4 v0 = ((const float4*)(h + (size_t)s0 * Hd))[t];
        float4 v1 = ((const float4*)(h + (size_t)s1 * Hd))[t];
        float4 v2 = ((const float4*)(h + (size_t)s2 * Hd))[t];
        float4 v3 = ((const float4*)(h + (size_t)s3 * Hd))[t];
        acc.x += (v0.x + v1.x) + (v2.x + v3.x);
        acc.y += (v0.y + v1.y) + (v2.y + v3.y);
        acc.z += (v0.z + v1.z) + (v2.z + v3.z);
        acc.w += (v0.w + v1.w) + (v2.w + v3.w);
    }
    for (; i < end; i++) {
        int s0 = g_esrc[i];
        float4 v0 = ((const float4*)(h + (size_t)s0 * Hd))[t];
        acc.x += v0.x; acc.y += v0.y; acc.z += v0.z; acc.w += v0.w;
    }
    ((float4*)(msg + (size_t)d * Hd))[t] = acc;
}

// ---------------- launch -----------------------------------------------------
extern "C" void kernel_launch(void* const* d_in, const int* in_sizes, int n_in,
                              void* d_out, int out_size)
{
    const float* text = (const float*)d_in[0];
    const float* tab  = (const float*)d_in[1];
    const float* str  = (const float*)d_in[2];
    const int*   ei   = (const int*)d_in[3];
    const float* Wg1  = (const float*)d_in[4];
    const float* bg1  = (const float*)d_in[5];
    const float* Wg2  = (const float*)d_in[6];
    const float* bg2  = (const float*)d_in[7];
    const float* We1  = (const float*)d_in[8];
    const float* be1  = (const float*)d_in[9];
    const float* We2  = (const float*)d_in[10];
    const float* be2  = (const float*)d_in[11];
    const float* Wself = (const float*)d_in[12];
    const float* Wnbr  = (const float*)d_in[13];
    float* out = (float*)d_out;
    const int nedges = in_sizes[3] / 2;

    void *pcnt, *pghid, *pnf, *pmsg, *phl, *ph1, *peo, *plists, *pwh, *pwl;
    void *pdeg;
    cudaGetSymbolAddress(&pcnt,   g_counts);
    cudaGetSymbolAddress(&pghid,  g_ghid);
    cudaGetSymbolAddress(&pnf,    g_nf);
    cudaGetSymbolAddress(&pmsg,   g_msg);
    cudaGetSymbolAddress(&phl,    g_hl);
    cudaGetSymbolAddress(&ph1,    g_h1);
    cudaGetSymbolAddress(&peo,    g_eout);
    cudaGetSymbolAddress(&plists, g_lists);
    cudaGetSymbolAddress(&pwh,    g_wbh);
    cudaGetSymbolAddress(&pwl,    g_wbl);
    cudaGetSymbolAddress(&pdeg,   g_deg);
    __nv_bfloat16* wbh = (__nv_bfloat16*)pwh;
    __nv_bfloat16* wbl = (__nv_bfloat16*)pwl;

    auto kG   = k_mma<3, false, false, false, 1, false>;
    auto kE1  = k_mma<1, true,  false, true,  2, true>;
    auto kE2  = k_mma<1, false, true,  false, 0, true>;
    auto kGNN = k_mma<2, false, false, false, 1, false>;
    cudaFuncSetAttribute(kG,   cudaFuncAttributeMaxDynamicSharedMemorySize, DSMEM);
    cudaFuncSetAttribute(kE1,  cudaFuncAttributeMaxDynamicSharedMemorySize, DSMEM);
    cudaFuncSetAttribute(kE2,  cudaFuncAttributeMaxDynamicSharedMemorySize, DSMEM);
    cudaFuncSetAttribute(kGNN, cudaFuncAttributeMaxDynamicSharedMemorySize, DSMEM);

    // ---- side stream: CSR build runs concurrently with gating/expert path ----
    cudaStream_t s2;
    cudaStreamCreateWithFlags(&s2, cudaStreamNonBlocking);
    cudaEvent_t evFork, evJoin;
    cudaEventCreateWithFlags(&evFork, cudaEventDisableTiming);
    cudaEventCreateWithFlags(&evJoin, cudaEventDisableTiming);

    cudaEventRecord(evFork, 0);
    cudaStreamWaitEvent(s2, evFork, 0);
    cudaMemsetAsync(pdeg, 0, sizeof(int) * Nn, s2);
    k_hist<<<CDIV(nedges, 256), 256, 0, s2>>>(ei, nedges);
    k_scan<<<1, 1024, 0, s2>>>(Nn);
    k_fill<<<CDIV(nedges, 256), 256, 0, s2>>>(ei, nedges);
    cudaEventRecord(evJoin, s2);

    // ---- main stream ----
    cudaMemsetAsync(pcnt, 0, sizeof(int) * NEx);

    // 0) pre-split weights into [n][k] bf16 hi/lo planes
    k_wprep<<<dim3(CDIV(768 * 128, 256), 1), 256>>>(Wg1,  wbh + OFF_G,  wbl + OFF_G,  768, 128, 768);
    k_wprep<<<dim3(CDIV(256 * 512, 256), NEx), 256>>>(We1, wbh + OFF_E1, wbl + OFF_E1, 256, 512, 256);
    k_wprep<<<dim3(CDIV(512 * 512, 256), NEx), 256>>>(We2, wbh + OFF_E2, wbl + OFF_E2, 512, 512, 512);
    k_wprep<<<dim3(CDIV(512 * 512, 256), 2), 256>>>(Wself, wbh + OFF_GNN,       wbl + OFF_GNN,       512, 512, 1024);
    k_wprep<<<dim3(CDIV(512 * 512, 256), 2), 256>>>(Wnbr,  wbh + OFF_GNN + 512, wbl + OFF_GNN + 512, 512, 512, 1024);

    const int MT = CDIV(Nn, 128);

    // 1) gating hidden: relu([text|tab|str] @ Wg1 + bg1)
    kG<<<dim3(1, MT), 256, DSMEM>>>(
        text, tab, str, wbh + OFF_G, wbl + OFF_G, bg1, (float*)pghid,
        nullptr, Nn, 3 * Ed, GHd);

    // 2) gating head: softmax top-2, build routing lists + per-node slots
    k_gate<<<CDIV(Nn, 32), 1024>>>(Wg2, bg2);

    // 3) expert MLP layer 1 (gathered rows, gelu), all 5 experts
    kE1<<<dim3(Hd / 128, MT, NEx), 256, DSMEM>>>(
        text, tab, str, wbh + OFF_E1, wbl + OFF_E1, be1, (float*)ph1,
        (const int*)plists, 0, Ed, Hd);

    // 4) expert MLP layer 2 -> dense eout, then per-node gated combine
    kE2<<<dim3(Hd / 128, MT, NEx), 256, DSMEM>>>(
        (const float*)ph1, nullptr, nullptr, wbh + OFF_E2, wbl + OFF_E2, be2,
        (float*)peo, (const int*)plists, 0, Hd, Hd);
    k_combine<<<Nn, 128>>>();

    // join: CSR must be ready before the first gather
    cudaStreamWaitEvent(0, evJoin, 0);

    // ---- GNN layer 0: h1 = relu([h | segsum(h)] @ [[Wself0],[Wnbr0]]) ----
    k_gather<<<CDIV(Nn, 2), 256>>>((const float*)pnf, (float*)pmsg);
    kGNN<<<dim3(Hd / 128, MT), 256, DSMEM>>>(
        (const float*)pnf, (const float*)pmsg, nullptr,
        wbh + OFF_GNN, wbl + OFF_GNN, nullptr, (float*)phl,
        nullptr, Nn, 2 * Hd, Hd);

    // ---- GNN layer 1 ----
    k_gather<<<CDIV(Nn, 2), 256>>>((const float*)phl, (float*)pmsg);
    kGNN<<<dim3(Hd / 128, MT), 256, DSMEM>>>(
        (const float*)phl, (const float*)pmsg, nullptr,
        wbh + OFF_GNN + (size_t)512 * 1024, wbl + OFF_GNN + (size_t)512 * 1024,
        nullptr, out, nullptr, Nn, 2 * Hd, Hd);
}